// round 5
// baseline (speedup 1.0000x reference)
#include <cuda_runtime.h>

// Problem constants
#define BB 4096   // batch
#define TT 512    // time steps
#define DD 8      // input dim
#define HH 64     // hidden
#define GG 256    // 4*H gates
#define TB 32     // batch tile per CTA
#define HS 68     // padded h row stride (conflict-free broadcast loads)
#define NT 128    // threads per CTA

// smem layout (floats):
//  wih0 [8][256] k-major   : 2048
//  whh0 [64][256] k-major  : 16384
//  wih1 [64][256] k-major  : 16384
//  whh1 [64][256] k-major  : 16384
//  b0, b1 (bih+bhh)        : 512
//  h0 [32][68], h1 [32][68]: 4352
//  x double buffer [2][32][8]: 512
#define SMEM_FLOATS (DD*GG + 3*HH*GG + 2*GG + 2*TB*HS + 2*TB*DD)
#define SMEM_BYTES  (SMEM_FLOATS * 4)

__device__ __forceinline__ float sigm(float z) {
    return 1.0f / (1.0f + __expf(-z));
}
__device__ __forceinline__ float tanh_f(float z) {
    return 2.0f / (1.0f + __expf(-2.0f * z)) - 1.0f;
}

#define FMA8(accp, hval, lo, hi)                                            \
    (accp)[0] += (hval)*(lo).x; (accp)[1] += (hval)*(lo).y;                 \
    (accp)[2] += (hval)*(lo).z; (accp)[3] += (hval)*(lo).w;                 \
    (accp)[4] += (hval)*(hi).x; (accp)[5] += (hval)*(hi).y;                 \
    (accp)[6] += (hval)*(hi).z; (accp)[7] += (hval)*(hi).w;

// acc[64]: acc[b*32 + gate_type*8 + u] for b in {0,1}, gate_type in {i,f,g,o}, u in 0..7
// hbuf: [TB][HS] row-major h state; wbuf: [64][256] k-major weights
__device__ __forceinline__ void gemm64(float* acc,
                                       const float* __restrict__ hbuf,
                                       const float* __restrict__ wbuf,
                                       int bA, int bB, int ug)
{
    #pragma unroll 2
    for (int k = 0; k < HH; k++) {
        float ha = hbuf[bA * HS + k];
        float hb = hbuf[bB * HS + k];
        const float4* wr = (const float4*)(wbuf + k * GG + ug * 8);
        #pragma unroll
        for (int g4 = 0; g4 < 4; g4++) {
            float4 lo = wr[g4 * 16];
            float4 hi = wr[g4 * 16 + 1];
            FMA8(acc + g4 * 8,      ha, lo, hi)
            FMA8(acc + 32 + g4 * 8, hb, lo, hi)
        }
    }
}

__device__ __forceinline__ void cell_update(const float* acc, float* c, float* nh)
{
    #pragma unroll
    for (int b = 0; b < 2; b++) {
        #pragma unroll
        for (int u = 0; u < 8; u++) {
            float iv = sigm(acc[b * 32 + 0 * 8 + u]);
            float fv = sigm(acc[b * 32 + 1 * 8 + u]);
            float gv = tanh_f(acc[b * 32 + 2 * 8 + u]);
            float ov = sigm(acc[b * 32 + 3 * 8 + u]);
            float cc = fv * c[b * 8 + u] + iv * gv;
            c[b * 8 + u]  = cc;
            nh[b * 8 + u] = ov * tanh_f(cc);
        }
    }
}

__global__ __launch_bounds__(NT, 1)
void lstm_fused(const float* __restrict__ x,
                const float* __restrict__ Wih0, const float* __restrict__ Whh0,
                const float* __restrict__ bih0, const float* __restrict__ bhh0,
                const float* __restrict__ Wih1, const float* __restrict__ Whh1,
                const float* __restrict__ bih1, const float* __restrict__ bhh1,
                const float* __restrict__ Wfc,  const float* __restrict__ bfc,
                float* __restrict__ out)
{
    extern __shared__ float sm[];
    float* s_wih0 = sm;                       // [8][256] k-major
    float* s_whh0 = s_wih0 + DD * GG;         // [64][256] k-major
    float* s_wih1 = s_whh0 + HH * GG;
    float* s_whh1 = s_wih1 + HH * GG;
    float* s_b0   = s_whh1 + HH * GG;         // [256]
    float* s_b1   = s_b0 + GG;
    float* s_h0   = s_b1 + GG;                // [32][68]
    float* s_h1   = s_h0 + TB * HS;
    float* s_x    = s_h1 + TB * HS;           // [2][32][8]

    const int tid = threadIdx.x;
    const int b0g = blockIdx.x * TB;

    // Weight load + transpose to k-major (coalesced gmem reads, one-time)
    for (int i = tid; i < GG * DD; i += NT) { int g = i >> 3, k = i & 7;  s_wih0[k * GG + g] = Wih0[i]; }
    for (int i = tid; i < GG * HH; i += NT) { int g = i >> 6, k = i & 63; s_whh0[k * GG + g] = Whh0[i]; }
    for (int i = tid; i < GG * HH; i += NT) { int g = i >> 6, k = i & 63; s_wih1[k * GG + g] = Wih1[i]; }
    for (int i = tid; i < GG * HH; i += NT) { int g = i >> 6, k = i & 63; s_whh1[k * GG + g] = Whh1[i]; }
    for (int i = tid; i < GG; i += NT) { s_b0[i] = bih0[i] + bhh0[i]; s_b1[i] = bih1[i] + bhh1[i]; }
    for (int i = tid; i < TB * HS; i += NT) { s_h0[i] = 0.f; s_h1[i] = 0.f; }
    // x for t = 0
    for (int i = tid; i < TB * DD; i += NT) {
        s_x[i] = x[(b0g + (i >> 3)) * (TT * DD) + (i & 7)];
    }
    __syncthreads();

    const int ug = tid & 7;        // unit group: units ug*8 .. ug*8+7
    const int bq = tid >> 3;       // batch pair index 0..15
    const int bA = bq * 2, bB = bA + 1;

    float c0[16], c1[16];
    #pragma unroll
    for (int i = 0; i < 16; i++) { c0[i] = 0.f; c1[i] = 0.f; }

    float acc[64];
    float nh[16];

    for (int t = 0; t < TT; t++) {
        const int cur = t & 1;

        // Prefetch x_{t+1} into registers (hidden under compute)
        float px0 = 0.f, px1 = 0.f;
        if (t + 1 < TT) {
            px0 = x[(b0g + (tid >> 3)) * (TT * DD) + (t + 1) * DD + (tid & 7)];
            px1 = x[(b0g + ((tid + NT) >> 3)) * (TT * DD) + (t + 1) * DD + (tid & 7)];
        }

        // ---------------- Layer 0 ----------------
        #pragma unroll
        for (int g4 = 0; g4 < 4; g4++) {
            #pragma unroll
            for (int u = 0; u < 8; u++) {
                float bv = s_b0[g4 * 64 + ug * 8 + u];
                acc[g4 * 8 + u]      = bv;
                acc[32 + g4 * 8 + u] = bv;
            }
        }
        // xg0 = x_t @ Wih0.T  (K = 8)
        {
            const float* xs = s_x + cur * (TB * DD);
            #pragma unroll
            for (int k = 0; k < DD; k++) {
                float ha = xs[bA * DD + k];
                float hb = xs[bB * DD + k];
                const float4* wr = (const float4*)(s_wih0 + k * GG + ug * 8);
                #pragma unroll
                for (int g4 = 0; g4 < 4; g4++) {
                    float4 lo = wr[g4 * 16];
                    float4 hi = wr[g4 * 16 + 1];
                    FMA8(acc + g4 * 8,      ha, lo, hi)
                    FMA8(acc + 32 + g4 * 8, hb, lo, hi)
                }
            }
        }
        // + h0_{t-1} @ Whh0.T
        gemm64(acc, s_h0, s_whh0, bA, bB, ug);
        cell_update(acc, c0, nh);

        __syncthreads();   // all gemm0 reads of s_h0 done
        #pragma unroll
        for (int b = 0; b < 2; b++) {
            #pragma unroll
            for (int u = 0; u < 8; u++)
                s_h0[(bA + b) * HS + ug * 8 + u] = nh[b * 8 + u];
        }
        if (t + 1 < TT) {
            s_x[(cur ^ 1) * (TB * DD) + tid]      = px0;
            s_x[(cur ^ 1) * (TB * DD) + tid + NT] = px1;
        }
        __syncthreads();   // s_h0 (= layer-1 input) ready

        // ---------------- Layer 1 ----------------
        #pragma unroll
        for (int g4 = 0; g4 < 4; g4++) {
            #pragma unroll
            for (int u = 0; u < 8; u++) {
                float bv = s_b1[g4 * 64 + ug * 8 + u];
                acc[g4 * 8 + u]      = bv;
                acc[32 + g4 * 8 + u] = bv;
            }
        }
        gemm64(acc, s_h0, s_wih1, bA, bB, ug);   // h1_t @ Wih1.T
        gemm64(acc, s_h1, s_whh1, bA, bB, ug);   // h2_{t-1} @ Whh1.T
        cell_update(acc, c1, nh);

        __syncthreads();   // all gemm1 reads of s_h1 done
        #pragma unroll
        for (int b = 0; b < 2; b++) {
            #pragma unroll
            for (int u = 0; u < 8; u++)
                s_h1[(bA + b) * HS + ug * 8 + u] = nh[b * 8 + u];
        }
        // next step's first read of s_h1 is after 2 more barriers; no extra sync needed
    }

    __syncthreads();
    // Final FC: out[b] = h2[b, T-1, :] . Wfc + bfc
    if (tid < TB) {
        float s = bfc[0];
        #pragma unroll
        for (int u = 0; u < HH; u++)
            s += s_h1[tid * HS + u] * Wfc[u];
        out[b0g + tid] = s;
    }
}

extern "C" void kernel_launch(void* const* d_in, const int* in_sizes, int n_in,
                              void* d_out, int out_size)
{
    (void)in_sizes; (void)n_in; (void)out_size;
    cudaFuncSetAttribute(lstm_fused, cudaFuncAttributeMaxDynamicSharedMemorySize, SMEM_BYTES);
    lstm_fused<<<BB / TB, NT, SMEM_BYTES>>>(
        (const float*)d_in[0],
        (const float*)d_in[1], (const float*)d_in[2],
        (const float*)d_in[3], (const float*)d_in[4],
        (const float*)d_in[5], (const float*)d_in[6],
        (const float*)d_in[7], (const float*)d_in[8],
        (const float*)d_in[9], (const float*)d_in[10],
        (float*)d_out);
}

// round 7
// speedup vs baseline: 26.0520x; 26.0520x over previous
#include <cuda_runtime.h>
#include <cuda_fp16.h>
#include <cstdint>

#define BB 4096
#define TT 512
#define DD 8
#define HH 64
#define TB 32
#define NT 256

// smem byte offsets; all tiles have 256B rows, 16B-chunk XOR swizzle
#define SA0 0        // A0: 32 rows  (k: [x 0..7][1 @8][0 9..15][h0 16..79])  8KB
#define SA1 8192     // A1: 32 rows  (k: [h0 0..63][h1 64..127])              8KB
#define SB0 16384    // B0: 256 rows (k: [Wih0 0..7][b0 @8][0][Whh0 16..79]) 64KB
#define SB1 81920    // B1: 256 rows (k: [Wih1 0..63][Whh1 64..127])         64KB
#define SMEM_TOTAL 147456

static __device__ __forceinline__ uint32_t smem_u32(const void* p){
    uint32_t a;
    asm("{ .reg .u64 t; cvta.to.shared.u64 t, %1; cvt.u32.u64 %0, t; }" : "=r"(a) : "l"(p));
    return a;
}
// swizzled byte offset within a tile: row*256 + chunk^(row&7) layout
static __device__ __forceinline__ uint32_t swb(int row, int kb){
    return (uint32_t)(row * 256 + ((((kb) >> 4) ^ (row & 7)) << 4) + ((kb) & 15));
}
static __device__ __forceinline__ float tanha(float x){
    float y; asm("tanh.approx.f32 %0, %1;" : "=f"(y) : "f"(x)); return y;
}
static __device__ __forceinline__ uint32_t pack2(float a, float b){
    __half2 h = __floats2half2_rn(a, b);
    return *(uint32_t*)&h;
}

#define LDSM4(addr, r0, r1, r2, r3) \
    asm volatile("ldmatrix.sync.aligned.m8n8.x4.shared.b16 {%0,%1,%2,%3}, [%4];" \
        : "=r"(r0), "=r"(r1), "=r"(r2), "=r"(r3) : "r"(addr))
#define LDSM2(addr, r0, r1) \
    asm volatile("ldmatrix.sync.aligned.m8n8.x2.shared.b16 {%0,%1}, [%2];" \
        : "=r"(r0), "=r"(r1) : "r"(addr))
#define MMA(accp, ap, b0_, b1_) \
    asm volatile("mma.sync.aligned.m16n8k16.row.col.f32.f16.f16.f32 " \
        "{%0,%1,%2,%3},{%4,%5,%6,%7},{%8,%9},{%0,%1,%2,%3};" \
        : "+f"((accp)[0]), "+f"((accp)[1]), "+f"((accp)[2]), "+f"((accp)[3]) \
        : "r"((ap)[0]), "r"((ap)[1]), "r"((ap)[2]), "r"((ap)[3]), "r"(b0_), "r"(b1_))

// warp computes z-tile [16 rows x 64 cols] = A[m0..+15, 0..16*KT) @ B[nbase..+63, ...]^T
template<int KTILES>
static __device__ __forceinline__ void gemm_tile(uint32_t abase, uint32_t bbase,
                                                 int m0, int nbase, int lane,
                                                 float acc[8][4])
{
    const int amat = lane >> 3;
    const int arow = m0 + (lane & 7) + (amat & 1) * 8;
    const uint32_t arb = abase + (uint32_t)(arow * 256);
    const int arx = arow & 7;
    const int apc = amat >> 1;
    uint32_t af[KTILES][4];
    #pragma unroll
    for (int kt = 0; kt < KTILES; kt++) {
        uint32_t ad = arb + (uint32_t)((((2 * kt + apc) ^ arx) << 4));
        LDSM4(ad, af[kt][0], af[kt][1], af[kt][2], af[kt][3]);
    }
    const int bl  = lane & 7;
    const int bco = lane >> 3;
    #pragma unroll
    for (int nt = 0; nt < 8; nt++) {
        const int brow = nbase + 8 * nt + bl;
        const uint32_t brb = bbase + (uint32_t)(brow * 256);
        const int brx = brow & 7;
        #pragma unroll
        for (int ktp = 0; ktp < KTILES / 2; ktp++) {
            uint32_t b0, b1, b2, b3;
            uint32_t bd = brb + (uint32_t)((((4 * ktp + bco) ^ brx) << 4));
            LDSM4(bd, b0, b1, b2, b3);
            MMA(acc[nt], af[2 * ktp],     b0, b1);
            MMA(acc[nt], af[2 * ktp + 1], b2, b3);
        }
        if (KTILES & 1) {
            const int kt = KTILES - 1;
            uint32_t b0, b1;
            uint32_t bd = brb + (uint32_t)((((2 * kt + (bco & 1)) ^ brx) << 4));
            LDSM2(bd, b0, b1);
            MMA(acc[nt], af[kt], b0, b1);
        }
    }
}

// column permutation (64-col period): n <-> (unit u, gate g)
// n = 64*(u/16) + 32*(g/2) + 8*((u%16)/4) + 2*(u%4) + (g%2)
static __device__ __forceinline__ void decode_n(int n, int& u, int& g){
    int blk = n >> 6, w64 = n & 63;
    int gp = w64 >> 5, rem = w64 & 31;
    int j = rem >> 3, pos = rem & 7;
    u = (blk << 4) + (j << 2) + (pos >> 1);
    g = (gp << 1) + (pos & 1);
}

__global__ void __launch_bounds__(NT, 1)
lstm_mma(const float* __restrict__ x,
         const float* __restrict__ Wih0, const float* __restrict__ Whh0,
         const float* __restrict__ bih0, const float* __restrict__ bhh0,
         const float* __restrict__ Wih1, const float* __restrict__ Whh1,
         const float* __restrict__ bih1, const float* __restrict__ bhh1,
         const float* __restrict__ Wfc,  const float* __restrict__ bfc,
         float* __restrict__ out)
{
    extern __shared__ char sm[];
    const uint32_t sbase = smem_u32(sm);
    const int tid = threadIdx.x, lane = tid & 31, w = tid >> 5;
    const int r = lane >> 2, cc = lane & 3;
    const int m0 = 16 * (w & 1);         // M tile rows
    const int q  = w >> 1;               // 64-col block
    const int U0 = 16 * q;               // unit base
    const int nbase = 64 * q;            // B row base
    const int b0g = blockIdx.x * TB;

    // zero A0 + A1
    for (int i = tid; i < 1024; i += NT) ((uint4*)sm)[i] = make_uint4(0, 0, 0, 0);

    // B0: [Wih0 | b0 | 0 | Whh0], permuted rows, swizzled
    for (int idx = tid; idx < 256 * 128; idx += NT) {
        int n = idx >> 7, k = idx & 127;
        int u, g; decode_n(n, u, g);
        int sr = g * 64 + u;
        float v = 0.f;
        if (k < 8)            v = Wih0[sr * DD + k];
        else if (k == 8)      v = bih0[sr] + bhh0[sr];
        else if (k >= 16 && k < 80) v = Whh0[sr * HH + (k - 16)];
        *(__half*)(sm + SB0 + swb(n, 2 * k)) = __float2half_rn(v);
    }
    // B1: [Wih1 | Whh1]
    for (int idx = tid; idx < 256 * 128; idx += NT) {
        int n = idx >> 7, k = idx & 127;
        int u, g; decode_n(n, u, g);
        int sr = g * 64 + u;
        float v = (k < 64) ? Wih1[sr * HH + k] : Whh1[sr * HH + (k - 64)];
        *(__half*)(sm + SB1 + swb(n, 2 * k)) = __float2half_rn(v);
    }

    // bias1 in regs (0.5-prescaled for sigmoid gates)
    float bi05[4], bf05[4], bg1[4], bo05[4];
    #pragma unroll
    for (int j = 0; j < 4; j++) {
        int u = U0 + 4 * j + cc;
        bi05[j] = 0.5f * (bih1[u]        + bhh1[u]);
        bf05[j] = 0.5f * (bih1[64 + u]   + bhh1[64 + u]);
        bg1[j]  =        (bih1[128 + u]  + bhh1[128 + u]);
        bo05[j] = 0.5f * (bih1[192 + u]  + bhh1[192 + u]);
    }
    __syncthreads();

    // A0 const-1 column (k=8) + x_0
    if (tid < TB) {
        *(__half*)(sm + SA0 + swb(tid, 16)) = __float2half_rn(1.0f);
        const float* xp = x + (size_t)(b0g + tid) * TT * DD;
        float4 xa = ((const float4*)xp)[0], xb = ((const float4*)xp)[1];
        uint4 v;
        v.x = pack2(xa.x, xa.y); v.y = pack2(xa.z, xa.w);
        v.z = pack2(xb.x, xb.y); v.w = pack2(xb.z, xb.w);
        *(uint4*)(sm + SA0 + (uint32_t)(tid * 256 + ((tid & 7) << 4))) = v;
    }
    __syncthreads();

    float c0s[8], c1s[8];
    #pragma unroll
    for (int i = 0; i < 8; i++) { c0s[i] = 0.f; c1s[i] = 0.f; }
    float acc[8][4];

    for (int t = 0; t < TT; t++) {
        // prefetch x_{t+1}
        float4 xa, xb;
        const bool hx = (tid < TB) && (t + 1 < TT);
        if (hx) {
            const float* xp = x + (size_t)(b0g + tid) * TT * DD + (size_t)(t + 1) * DD;
            xa = ((const float4*)xp)[0]; xb = ((const float4*)xp)[1];
        }

        // ---- layer 0: z0 = [x|1|h0] @ B0^T ----
        #pragma unroll
        for (int nt = 0; nt < 8; nt++)
            { acc[nt][0] = 0.f; acc[nt][1] = 0.f; acc[nt][2] = 0.f; acc[nt][3] = 0.f; }
        gemm_tile<5>(sbase + SA0, sbase + SB0, m0, nbase, lane, acc);
        __syncthreads();

        if (hx) {
            uint4 v;
            v.x = pack2(xa.x, xa.y); v.y = pack2(xa.z, xa.w);
            v.z = pack2(xb.x, xb.y); v.w = pack2(xb.z, xb.w);
            *(uint4*)(sm + SA0 + (uint32_t)(tid * 256 + ((tid & 7) << 4))) = v;
        }
        // epilogue 0
        #pragma unroll
        for (int j = 0; j < 4; j++) {
            #pragma unroll
            for (int rh = 0; rh < 2; rh++) {
                float zi = acc[j][rh * 2],     zf = acc[j][rh * 2 + 1];
                float zg = acc[4 + j][rh * 2], zo = acc[4 + j][rh * 2 + 1];
                float I = 0.5f * tanha(0.5f * zi) + 0.5f;
                float F = 0.5f * tanha(0.5f * zf) + 0.5f;
                float G = tanha(zg);
                float O = 0.5f * tanha(0.5f * zo) + 0.5f;
                int ci = j * 2 + rh;
                float cn = F * c0s[ci] + I * G;
                c0s[ci] = cn;
                float h = O * tanha(cn);
                int u = U0 + 4 * j + cc;
                int row = m0 + r + rh * 8;
                __half hh = __float2half_rn(h);
                *(__half*)(sm + SA0 + swb(row, 2 * (16 + u))) = hh;  // layer-0 recurrence
                *(__half*)(sm + SA1 + swb(row, 2 * u)) = hh;         // layer-1 input
            }
        }
        __syncthreads();

        // ---- layer 1: z1 = [h0|h1] @ B1^T ----
        #pragma unroll
        for (int nt = 0; nt < 8; nt++)
            { acc[nt][0] = 0.f; acc[nt][1] = 0.f; acc[nt][2] = 0.f; acc[nt][3] = 0.f; }
        gemm_tile<8>(sbase + SA1, sbase + SB1, m0, nbase, lane, acc);
        __syncthreads();

        // epilogue 1 (bias1 added here)
        #pragma unroll
        for (int j = 0; j < 4; j++) {
            #pragma unroll
            for (int rh = 0; rh < 2; rh++) {
                float zi = acc[j][rh * 2],     zf = acc[j][rh * 2 + 1];
                float zg = acc[4 + j][rh * 2], zo = acc[4 + j][rh * 2 + 1];
                float I = 0.5f * tanha(0.5f * zi + bi05[j]) + 0.5f;
                float F = 0.5f * tanha(0.5f * zf + bf05[j]) + 0.5f;
                float G = tanha(zg + bg1[j]);
                float O = 0.5f * tanha(0.5f * zo + bo05[j]) + 0.5f;
                int ci = j * 2 + rh;
                float cn = F * c1s[ci] + I * G;
                c1s[ci] = cn;
                float h = O * tanha(cn);
                int u = U0 + 4 * j + cc;
                int row = m0 + r + rh * 8;
                *(__half*)(sm + SA1 + swb(row, 2 * (64 + u))) = __float2half_rn(h);
            }
        }
        // epilogue-1 writes ordered before next gemm1 by the sync after next gemm0
    }

    __syncthreads();
    // final FC: out[b] = h1_last . Wfc + bfc
    if (tid < TB) {
        float s = bfc[0];
        #pragma unroll 8
        for (int u = 0; u < HH; u++)
            s += __half2float(*(const __half*)(sm + SA1 + swb(tid, 2 * (64 + u)))) * Wfc[u];
        out[b0g + tid] = s;
    }
}

extern "C" void kernel_launch(void* const* d_in, const int* in_sizes, int n_in,
                              void* d_out, int out_size)
{
    (void)in_sizes; (void)n_in; (void)out_size;
    cudaFuncSetAttribute(lstm_mma, cudaFuncAttributeMaxDynamicSharedMemorySize, SMEM_TOTAL);
    lstm_mma<<<BB / TB, NT, SMEM_TOTAL>>>(
        (const float*)d_in[0],
        (const float*)d_in[1], (const float*)d_in[2],
        (const float*)d_in[3], (const float*)d_in[4],
        (const float*)d_in[5], (const float*)d_in[6],
        (const float*)d_in[7], (const float*)d_in[8],
        (const float*)d_in[9], (const float*)d_in[10],
        (float*)d_out);
}